// round 13
// baseline (speedup 1.0000x reference)
#include <cuda_runtime.h>
#include <math.h>

#define BN    8
#define SSUP  25
#define TTGT  75
#define CCLS  5
#define NIMG  800     // 200 support + 600 target
#define NSUP  200
#define DFEAT 2304
#define EPSN  1e-8f

typedef unsigned long long u64;

// Padded intermediate layouts (zero borders, vector-load friendly):
// A1: [64][44][44] valid [0..41][0..41]
// A2: [64][24][24] valid at [h+1][w+1], h,w<=20
// A3: [64][14][16] valid at [h+1][w+1], h,w<=10
#define A1_RS 44
#define A1_PS (44*44)
#define A1_IMG (64*A1_PS)
#define A2_RS 24
#define A2_PS (24*24)
#define A2_IMG (64*A2_PS)
#define A3_RS 16
#define A3_PS (14*16)
#define A3_IMG (64*A3_PS)

__device__ __align__(16) float g_a1[NIMG * A1_IMG + 64];
__device__ __align__(16) float g_a2[NIMG * A2_IMG + 64];
__device__ __align__(16) float g_a3[NIMG * A3_IMG + 64];
__device__ __align__(16) float g_emb[NIMG * DFEAT];
__device__ float g_protos[BN * CCLS * DFEAT];
__device__ float g_pnorm[BN * CCLS];

// ---- packed f32x2 helpers (sm_103a FFMA2 path) ----
__device__ __forceinline__ u64 dup2(float v) {
    u64 r; unsigned u = __float_as_uint(v);
    asm("mov.b64 %0, {%1, %2};" : "=l"(r) : "r"(u), "r"(u));
    return r;
}
__device__ __forceinline__ u64 fma2(u64 a, u64 b, u64 c) {
    u64 d;
    asm("fma.rn.f32x2 %0, %1, %2, %3;" : "=l"(d) : "l"(a), "l"(b), "l"(c));
    return d;
}
__device__ __forceinline__ float2 unpack2(u64 v) {
    unsigned lo, hi;
    asm("mov.b64 {%0, %1}, %2;" : "=r"(lo), "=r"(hi) : "l"(v));
    return make_float2(__uint_as_float(lo), __uint_as_float(hi));
}

// Zero the padding borders of A1/A2/A3 (never touched by conv writers).
__global__ void zero_borders_k()
{
    const long long id = (long long)blockIdx.x * 256 + threadIdx.x;
    const int which = blockIdx.y;
    if (which == 0) {                         // A1: 172 border cells / chan
        if (id >= (long long)NIMG * 64 * 172) return;
        const int j = (int)(id % 172);
        const long long nc = id / 172;
        int r, c;
        if (j < 88) { r = 42 + j / 44; c = j % 44; }
        else { int j2 = j - 88; r = j2 >> 1; c = 42 + (j2 & 1); }
        g_a1[nc * A1_PS + r * A1_RS + c] = 0.f;
    } else if (which == 1) {                  // A2: 135 border cells / chan
        if (id >= (long long)NIMG * 64 * 135) return;
        const int j = (int)(id % 135);
        const long long nc = id / 135;
        int r, c;
        if (j < 72) { int rs = j / 24; r = (rs == 0) ? 0 : 21 + rs; c = j % 24; }
        else { int j2 = j - 72; r = 1 + j2 / 3; int m = j2 % 3; c = (m == 0) ? 0 : 21 + m; }
        g_a2[nc * A2_PS + r * A2_RS + c] = 0.f;
    } else {                                  // A3: 103 border cells / chan
        if (id >= (long long)NIMG * 64 * 103) return;
        const int j = (int)(id % 103);
        const long long nc = id / 103;
        int r, c;
        if (j < 48) { int rs = j / 16; r = (rs == 0) ? 0 : 11 + rs; c = j % 16; }
        else { int j2 = j - 48; r = 1 + j2 / 5; int m = j2 % 5; c = (m == 0) ? 0 : 11 + m; }
        g_a3[nc * A3_PS + r * A3_RS + c] = 0.f;
    }
}

// Direct conv, padded input, stride 2, 3x3, no bounds checks.
// COG=16: each thread computes 16 output channels (8 FFMA2 oc-pairs) x 4
// pixels. Weights in smem as [cin][k][oc16], read as broadcast LDS.128.
template <int CIN, int RS, int PS, int HOUT, int ORS, int OPS, int OSH, int TPB>
__device__ __forceinline__ void conv_body16(
    const float* __restrict__ base,
    const float* __restrict__ W,
    const float* __restrict__ bias,
    float* __restrict__ outp,
    int cog, int task)
{
    constexpr int WT = (HOUT + 3) / 4;
    const int tid = threadIdx.x;

    __shared__ __align__(16) float sw[16 * CIN * 9];  // [cin][k][oc16]
    for (int i = tid; i < 16 * CIN * 9; i += TPB) {
        const int oc  = i & 15;
        const int k   = (i >> 4) % 9;
        const int cin = i / 144;
        sw[i] = __ldg(W + ((size_t)(cog + oc) * CIN + cin) * 9 + k);
    }
    __syncthreads();

    if (task >= HOUT * WT) return;
    const int h  = task / WT;
    const int w0 = (task % WT) * 4;
    const int r0 = 2 * h;
    const int c0 = 2 * w0;

    u64 acc[8][4];
#pragma unroll
    for (int q = 0; q < 8; q++)
#pragma unroll
        for (int p = 0; p < 4; p++) acc[q][p] = 0ull;

    const float* ip0 = base + (size_t)r0 * RS + c0;

#pragma unroll 2
    for (int cin = 0; cin < CIN; cin++) {
        const float* ip = ip0 + (size_t)cin * PS;
#pragma unroll
        for (int kh = 0; kh < 3; kh++) {
            float fv[12];
#pragma unroll
            for (int v = 0; v < 3; v++)
                *(float4*)&fv[v * 4] = *(const float4*)(ip + kh * RS + v * 4);
            u64 dv[9];
#pragma unroll
            for (int j = 0; j < 9; j++) dv[j] = dup2(fv[j]);
#pragma unroll
            for (int kw = 0; kw < 3; kw++) {
                const ulonglong2* wrow =
                    (const ulonglong2*)&sw[(cin * 9 + kh * 3 + kw) * 16];
                const ulonglong2 wA = wrow[0];
                const ulonglong2 wB = wrow[1];
                const ulonglong2 wC = wrow[2];
                const ulonglong2 wD = wrow[3];
                const u64 wp[8] = {wA.x, wA.y, wB.x, wB.y, wC.x, wC.y, wD.x, wD.y};
#pragma unroll
                for (int q = 0; q < 8; q++)
#pragma unroll
                    for (int p = 0; p < 4; p++)
                        acc[q][p] = fma2(dv[2 * p + kw], wp[q], acc[q][p]);
            }
        }
    }

#pragma unroll
    for (int q = 0; q < 8; q++) {
        const int co0 = cog + 2 * q;
        const float b0 = __ldg(bias + co0);
        const float b1 = __ldg(bias + co0 + 1);
#pragma unroll
        for (int p = 0; p < 4; p++) {
            const int w = w0 + p;
            if (w < HOUT) {
                const float2 v = unpack2(acc[q][p]);
                outp[((size_t)co0       * OPS) + (h + OSH) * ORS + (w + OSH)] = fmaxf(v.x + b0, 0.f);
                outp[((size_t)(co0 + 1) * OPS) + (h + OSH) * ORS + (w + OSH)] = fmaxf(v.y + b1, 0.f);
            }
        }
    }
}

// Layer 1 (harness input, unpadded -> masked scalar loads), writes padded A1.
__global__ void __launch_bounds__(128)
conv1_k(const float* __restrict__ xs, const float* __restrict__ xt,
        const float* __restrict__ W, const float* __restrict__ b)
{
    const int n   = blockIdx.z;
    const int cog = blockIdx.y * 8;
    const int tid = threadIdx.x;
    const int task = blockIdx.x * 128 + tid;

    __shared__ __align__(16) float sw[8 * 3 * 9];
    for (int i = tid; i < 8 * 3 * 9; i += 128) {
        const int oc = i & 7, k = (i >> 3) % 9, cin = i / 72;
        sw[i] = __ldg(W + ((size_t)(cog + oc) * 3 + cin) * 9 + k);
    }
    __syncthreads();

    if (task >= 42 * 11) return;
    const int h  = task / 11;
    const int w0 = (task % 11) * 4;
    const int r0 = 2 * h, c0 = 2 * w0;

    const float* base = (n < NSUP) ? xs + (size_t)n * 3 * 84 * 84
                                   : xt + (size_t)(n - NSUP) * 3 * 84 * 84;
    float* outp = g_a1 + (size_t)n * A1_IMG;

    u64 acc[4][4];
#pragma unroll
    for (int q = 0; q < 4; q++)
#pragma unroll
        for (int p = 0; p < 4; p++) acc[q][p] = 0ull;

#pragma unroll
    for (int cin = 0; cin < 3; cin++) {
        const float* ip = base + (size_t)cin * 84 * 84;
#pragma unroll
        for (int kh = 0; kh < 3; kh++) {
            const int r = r0 + kh;
            const bool rok = (r < 84);
            u64 dv[9];
#pragma unroll
            for (int kc = 0; kc < 9; kc++) {
                const int c = c0 + kc;
                const float v = (rok && c < 84) ? __ldg(ip + r * 84 + c) : 0.f;
                dv[kc] = dup2(v);
            }
#pragma unroll
            for (int kw = 0; kw < 3; kw++) {
                const u64* wrow = (const u64*)&sw[cin * 72 + (kh * 3 + kw) * 8];
#pragma unroll
                for (int q = 0; q < 4; q++) {
                    const u64 wp = wrow[q];
#pragma unroll
                    for (int p = 0; p < 4; p++)
                        acc[q][p] = fma2(dv[2 * p + kw], wp, acc[q][p]);
                }
            }
        }
    }

#pragma unroll
    for (int q = 0; q < 4; q++) {
        const int co0 = cog + 2 * q;
        const float b0 = __ldg(b + co0);
        const float b1 = __ldg(b + co0 + 1);
#pragma unroll
        for (int p = 0; p < 4; p++) {
            const int w = w0 + p;
            if (w < 42) {
                const float2 v = unpack2(acc[q][p]);
                outp[(size_t)co0       * A1_PS + h * A1_RS + w] = fmaxf(v.x + b0, 0.f);
                outp[(size_t)(co0 + 1) * A1_PS + h * A1_RS + w] = fmaxf(v.y + b1, 0.f);
            }
        }
    }
}

// Layer 2: A1 -> A2, 126 tasks/img, 2 img/block (256 threads)
__global__ void __launch_bounds__(256)
conv2_k(const float* __restrict__ W, const float* __restrict__ b)
{
    const int il = threadIdx.x >> 7;
    const int task = threadIdx.x & 127;
    const int n = blockIdx.y * 2 + il;
    const int cog = blockIdx.x * 16;
    conv_body16<64, A1_RS, A1_PS, 21, A2_RS, A2_PS, 1, 256>(
        g_a1 + (size_t)n * A1_IMG, W, b, g_a2 + (size_t)n * A2_IMG, cog, task);
}

// Layer 3: A2 -> A3, 33 tasks/img, 8 img/block (264 threads)
__global__ void __launch_bounds__(264)
conv3_k(const float* __restrict__ W, const float* __restrict__ b)
{
    const int il = threadIdx.x / 33;
    const int task = threadIdx.x % 33;
    const int n = blockIdx.y * 8 + il;
    const int cog = blockIdx.x * 16;
    conv_body16<64, A2_RS, A2_PS, 11, A3_RS, A3_PS, 1, 264>(
        g_a2 + (size_t)n * A2_IMG, W, b, g_a3 + (size_t)n * A3_IMG, cog, task);
}

// Layer 4: A3 -> emb (dense), 12 tasks/img, 20 img/block (240 threads)
__global__ void __launch_bounds__(240)
conv4_k(const float* __restrict__ W, const float* __restrict__ b)
{
    const int il = threadIdx.x / 12;
    const int task = threadIdx.x % 12;
    const int n = blockIdx.y * 20 + il;
    const int cog = blockIdx.x * 16;
    conv_body16<64, A3_RS, A3_PS, 6, 6, 36, 0, 240>(
        g_a3 + (size_t)n * A3_IMG, W, b, g_emb + (size_t)n * DFEAT, cog, task);
}

// Prototypes: proto[b][c][d] = sum_{s: y%5==c} emb / CAP ; plus ||proto||.
__global__ void proto_k(const int* __restrict__ y)
{
    const int b = blockIdx.x / CCLS;
    const int c = blockIdx.x % CCLS;
    const int tid = threadIdx.x;
    __shared__ float sel[SSUP];
    if (tid < SSUP)
        sel[tid] = ((y[b * SSUP + tid] % CCLS) == c) ? 0.2f : 0.f;
    __syncthreads();

    float sq = 0.f;
    for (int d = tid; d < DFEAT; d += 256) {
        float s = 0.f;
#pragma unroll 5
        for (int k = 0; k < SSUP; k++)
            s += sel[k] * g_emb[(size_t)(b * SSUP + k) * DFEAT + d];
        g_protos[(size_t)(b * CCLS + c) * DFEAT + d] = s;
        sq += s * s;
    }
    __shared__ float red[256];
    red[tid] = sq;
    __syncthreads();
    for (int off = 128; off > 0; off >>= 1) {
        if (tid < off) red[tid] += red[tid + off];
        __syncthreads();
    }
    if (tid == 0) g_pnorm[blockIdx.x] = sqrtf(red[0]);
}

// Cosine logits
__global__ void preds_k(float* __restrict__ out)
{
    const int bt = blockIdx.x;
    const int b  = bt / TTGT;
    const int tid = threadIdx.x;
    const float* te = g_emb + (size_t)(NSUP + bt) * DFEAT;
    const float* pr = g_protos + (size_t)b * CCLS * DFEAT;

    float dot[CCLS] = {0.f, 0.f, 0.f, 0.f, 0.f};
    float nn = 0.f;
    for (int d = tid; d < DFEAT; d += 128) {
        const float tv = te[d];
        nn += tv * tv;
#pragma unroll
        for (int c = 0; c < CCLS; c++)
            dot[c] += tv * pr[(size_t)c * DFEAT + d];
    }

    __shared__ float red[6][128];
    red[0][tid] = nn;
#pragma unroll
    for (int c = 0; c < CCLS; c++) red[c + 1][tid] = dot[c];
    __syncthreads();
    for (int off = 64; off > 0; off >>= 1) {
        if (tid < off) {
#pragma unroll
            for (int j = 0; j < 6; j++) red[j][tid] += red[j][tid + off];
        }
        __syncthreads();
    }
    if (tid < CCLS) {
        const float tn = fmaxf(sqrtf(red[0][0]), EPSN);
        const float pn = fmaxf(g_pnorm[b * CCLS + tid], EPSN);
        out[bt * CCLS + tid] = red[1 + tid][0] / (tn * pn);
    }
}

extern "C" void kernel_launch(void* const* d_in, const int* in_sizes, int n_in,
                              void* d_out, int out_size)
{
    (void)in_sizes; (void)n_in; (void)out_size;
    const float* xs = (const float*)d_in[0];
    const float* xt = (const float*)d_in[1];
    const int*   y  = (const int*)d_in[2];
    const float* W1 = (const float*)d_in[3];
    const float* b1 = (const float*)d_in[4];
    const float* W2 = (const float*)d_in[5];
    const float* b2 = (const float*)d_in[6];
    const float* W3 = (const float*)d_in[7];
    const float* b3 = (const float*)d_in[8];
    const float* W4 = (const float*)d_in[9];
    const float* b4 = (const float*)d_in[10];
    float* out = (float*)d_out;

    zero_borders_k<<<dim3(34400, 3), 256>>>();

    conv1_k<<<dim3(4, 8, NIMG), 128>>>(xs, xt, W1, b1);
    conv2_k<<<dim3(4, NIMG / 2), 256>>>(W2, b2);
    conv3_k<<<dim3(4, NIMG / 8), 264>>>(W3, b3);
    conv4_k<<<dim3(4, NIMG / 20), 240>>>(W4, b4);

    proto_k<<<BN * CCLS, 256>>>(y);
    preds_k<<<BN * TTGT, 128>>>(out);
}

// round 14
// speedup vs baseline: 1.1406x; 1.1406x over previous
#include <cuda_runtime.h>
#include <math.h>

#define BN    8
#define SSUP  25
#define TTGT  75
#define CCLS  5
#define NIMG  800     // 200 support + 600 target
#define NSUP  200
#define DFEAT 2304
#define EPSN  1e-8f

typedef unsigned long long u64;

// Padded intermediate layouts (zero borders, vector-load friendly):
// A1: [64][44][44] valid [0..41][0..41]
// A2: [64][24][24] valid at [h+1][w+1], h,w<=20
// A3: [64][14][16] valid at [h+1][w+1], h,w<=10
#define A1_RS 44
#define A1_PS (44*44)
#define A1_IMG (64*A1_PS)
#define A2_RS 24
#define A2_PS (24*24)
#define A2_IMG (64*A2_PS)
#define A3_RS 16
#define A3_PS (14*16)
#define A3_IMG (64*A3_PS)

__device__ __align__(16) float g_a1[NIMG * A1_IMG + 64];
__device__ __align__(16) float g_a2[NIMG * A2_IMG + 64];
__device__ __align__(16) float g_a3[NIMG * A3_IMG + 64];
__device__ __align__(16) float g_emb[NIMG * DFEAT];
__device__ float g_protos[BN * CCLS * DFEAT];
__device__ float g_pnorm[BN * CCLS];

// ---- packed f32x2 helpers (sm_103a FFMA2 path) ----
__device__ __forceinline__ u64 dup2(float v) {
    u64 r; unsigned u = __float_as_uint(v);
    asm("mov.b64 %0, {%1, %2};" : "=l"(r) : "r"(u), "r"(u));
    return r;
}
__device__ __forceinline__ u64 fma2(u64 a, u64 b, u64 c) {
    u64 d;
    asm("fma.rn.f32x2 %0, %1, %2, %3;" : "=l"(d) : "l"(a), "l"(b), "l"(c));
    return d;
}
__device__ __forceinline__ float2 unpack2(u64 v) {
    unsigned lo, hi;
    asm("mov.b64 {%0, %1}, %2;" : "=r"(lo), "=r"(hi) : "l"(v));
    return make_float2(__uint_as_float(lo), __uint_as_float(hi));
}

// Zero the padding borders of A1/A2/A3 (never touched by conv writers).
__global__ void zero_borders_k()
{
    const long long id = (long long)blockIdx.x * 256 + threadIdx.x;
    const int which = blockIdx.y;
    if (which == 0) {                         // A1: 172 border cells / chan
        if (id >= (long long)NIMG * 64 * 172) return;
        const int j = (int)(id % 172);
        const long long nc = id / 172;
        int r, c;
        if (j < 88) { r = 42 + j / 44; c = j % 44; }
        else { int j2 = j - 88; r = j2 >> 1; c = 42 + (j2 & 1); }
        g_a1[nc * A1_PS + r * A1_RS + c] = 0.f;
    } else if (which == 1) {                  // A2: 135 border cells / chan
        if (id >= (long long)NIMG * 64 * 135) return;
        const int j = (int)(id % 135);
        const long long nc = id / 135;
        int r, c;
        if (j < 72) { int rs = j / 24; r = (rs == 0) ? 0 : 21 + rs; c = j % 24; }
        else { int j2 = j - 72; r = 1 + j2 / 3; int m = j2 % 3; c = (m == 0) ? 0 : 21 + m; }
        g_a2[nc * A2_PS + r * A2_RS + c] = 0.f;
    } else {                                  // A3: 103 border cells / chan
        if (id >= (long long)NIMG * 64 * 103) return;
        const int j = (int)(id % 103);
        const long long nc = id / 103;
        int r, c;
        if (j < 48) { int rs = j / 16; r = (rs == 0) ? 0 : 11 + rs; c = j % 16; }
        else { int j2 = j - 48; r = 1 + j2 / 5; int m = j2 % 5; c = (m == 0) ? 0 : 11 + m; }
        g_a3[nc * A3_PS + r * A3_RS + c] = 0.f;
    }
}

// Direct conv, padded input, stride 2, 3x3, no bounds checks.
// COG=16: each thread computes 16 output channels (8 FFMA2 oc-pairs) x 4
// pixels. Weights in smem as [cin][k][oc16], read as broadcast LDS.128.
template <int CIN, int RS, int PS, int HOUT, int ORS, int OPS, int OSH, int TPB>
__device__ __forceinline__ void conv_body16(
    const float* __restrict__ base,
    const float* __restrict__ W,
    const float* __restrict__ bias,
    float* __restrict__ outp,
    int cog, int task)
{
    constexpr int WT = (HOUT + 3) / 4;
    const int tid = threadIdx.x;

    __shared__ __align__(16) float sw[16 * CIN * 9];  // [cin][k][oc16]
    for (int i = tid; i < 16 * CIN * 9; i += TPB) {
        const int oc  = i & 15;
        const int k   = (i >> 4) % 9;
        const int cin = i / 144;
        sw[i] = __ldg(W + ((size_t)(cog + oc) * CIN + cin) * 9 + k);
    }
    __syncthreads();

    if (task >= HOUT * WT) return;
    const int h  = task / WT;
    const int w0 = (task % WT) * 4;
    const int r0 = 2 * h;
    const int c0 = 2 * w0;

    u64 acc[8][4];
#pragma unroll
    for (int q = 0; q < 8; q++)
#pragma unroll
        for (int p = 0; p < 4; p++) acc[q][p] = 0ull;

    const float* ip0 = base + (size_t)r0 * RS + c0;

#pragma unroll 2
    for (int cin = 0; cin < CIN; cin++) {
        const float* ip = ip0 + (size_t)cin * PS;
#pragma unroll
        for (int kh = 0; kh < 3; kh++) {
            float fv[12];
#pragma unroll
            for (int v = 0; v < 3; v++)
                *(float4*)&fv[v * 4] = *(const float4*)(ip + kh * RS + v * 4);
            u64 dv[9];
#pragma unroll
            for (int j = 0; j < 9; j++) dv[j] = dup2(fv[j]);
#pragma unroll
            for (int kw = 0; kw < 3; kw++) {
                const ulonglong2* wrow =
                    (const ulonglong2*)&sw[(cin * 9 + kh * 3 + kw) * 16];
                const ulonglong2 wA = wrow[0];
                const ulonglong2 wB = wrow[1];
                const ulonglong2 wC = wrow[2];
                const ulonglong2 wD = wrow[3];
                const u64 wp[8] = {wA.x, wA.y, wB.x, wB.y, wC.x, wC.y, wD.x, wD.y};
#pragma unroll
                for (int q = 0; q < 8; q++)
#pragma unroll
                    for (int p = 0; p < 4; p++)
                        acc[q][p] = fma2(dv[2 * p + kw], wp[q], acc[q][p]);
            }
        }
    }

#pragma unroll
    for (int q = 0; q < 8; q++) {
        const int co0 = cog + 2 * q;
        const float b0 = __ldg(bias + co0);
        const float b1 = __ldg(bias + co0 + 1);
#pragma unroll
        for (int p = 0; p < 4; p++) {
            const int w = w0 + p;
            if (w < HOUT) {
                const float2 v = unpack2(acc[q][p]);
                outp[((size_t)co0       * OPS) + (h + OSH) * ORS + (w + OSH)] = fmaxf(v.x + b0, 0.f);
                outp[((size_t)(co0 + 1) * OPS) + (h + OSH) * ORS + (w + OSH)] = fmaxf(v.y + b1, 0.f);
            }
        }
    }
}

// Layer 1 (harness input, unpadded -> masked scalar loads), COG=16,
// writes padded A1. blockIdx: x = task chunk, y = cog16 group, z = image.
__global__ void __launch_bounds__(128)
conv1_k(const float* __restrict__ xs, const float* __restrict__ xt,
        const float* __restrict__ W, const float* __restrict__ b)
{
    const int n   = blockIdx.z;
    const int cog = blockIdx.y * 16;
    const int tid = threadIdx.x;
    const int task = blockIdx.x * 128 + tid;

    __shared__ __align__(16) float sw[16 * 3 * 9];   // [cin][k][oc16]
    for (int i = tid; i < 16 * 3 * 9; i += 128) {
        const int oc = i & 15, k = (i >> 4) % 9, cin = i / 144;
        sw[i] = __ldg(W + ((size_t)(cog + oc) * 3 + cin) * 9 + k);
    }
    __syncthreads();

    if (task >= 42 * 11) return;
    const int h  = task / 11;
    const int w0 = (task % 11) * 4;
    const int r0 = 2 * h, c0 = 2 * w0;

    const float* base = (n < NSUP) ? xs + (size_t)n * 3 * 84 * 84
                                   : xt + (size_t)(n - NSUP) * 3 * 84 * 84;
    float* outp = g_a1 + (size_t)n * A1_IMG;

    u64 acc[8][4];
#pragma unroll
    for (int q = 0; q < 8; q++)
#pragma unroll
        for (int p = 0; p < 4; p++) acc[q][p] = 0ull;

#pragma unroll
    for (int cin = 0; cin < 3; cin++) {
        const float* ip = base + (size_t)cin * 84 * 84;
#pragma unroll
        for (int kh = 0; kh < 3; kh++) {
            const int r = r0 + kh;
            const bool rok = (r < 84);
            u64 dv[9];
#pragma unroll
            for (int kc = 0; kc < 9; kc++) {
                const int c = c0 + kc;
                const float v = (rok && c < 84) ? __ldg(ip + r * 84 + c) : 0.f;
                dv[kc] = dup2(v);
            }
#pragma unroll
            for (int kw = 0; kw < 3; kw++) {
                const ulonglong2* wrow =
                    (const ulonglong2*)&sw[(cin * 9 + kh * 3 + kw) * 16];
                const ulonglong2 wA = wrow[0];
                const ulonglong2 wB = wrow[1];
                const ulonglong2 wC = wrow[2];
                const ulonglong2 wD = wrow[3];
                const u64 wp[8] = {wA.x, wA.y, wB.x, wB.y, wC.x, wC.y, wD.x, wD.y};
#pragma unroll
                for (int q = 0; q < 8; q++)
#pragma unroll
                    for (int p = 0; p < 4; p++)
                        acc[q][p] = fma2(dv[2 * p + kw], wp[q], acc[q][p]);
            }
        }
    }

#pragma unroll
    for (int q = 0; q < 8; q++) {
        const int co0 = cog + 2 * q;
        const float b0 = __ldg(b + co0);
        const float b1 = __ldg(b + co0 + 1);
#pragma unroll
        for (int p = 0; p < 4; p++) {
            const int w = w0 + p;
            if (w < 42) {
                const float2 v = unpack2(acc[q][p]);
                outp[(size_t)co0       * A1_PS + h * A1_RS + w] = fmaxf(v.x + b0, 0.f);
                outp[(size_t)(co0 + 1) * A1_PS + h * A1_RS + w] = fmaxf(v.y + b1, 0.f);
            }
        }
    }
}

// Layer 2: A1 -> A2, 126 tasks/img, 1 img/block, 4 cog16-groups
__global__ void __launch_bounds__(128, 3)
conv2_k(const float* __restrict__ W, const float* __restrict__ b)
{
    const int n = blockIdx.y;
    const int cog = blockIdx.x * 16;
    conv_body16<64, A1_RS, A1_PS, 21, A2_RS, A2_PS, 1, 128>(
        g_a1 + (size_t)n * A1_IMG, W, b, g_a2 + (size_t)n * A2_IMG,
        cog, threadIdx.x);
}

// Layer 3: A2 -> A3, 33 tasks/img, 4 img/block (132 threads)
__global__ void __launch_bounds__(132, 3)
conv3_k(const float* __restrict__ W, const float* __restrict__ b)
{
    const int il = threadIdx.x / 33;
    const int task = threadIdx.x % 33;
    const int n = blockIdx.y * 4 + il;
    const int cog = blockIdx.x * 16;
    conv_body16<64, A2_RS, A2_PS, 11, A3_RS, A3_PS, 1, 132>(
        g_a2 + (size_t)n * A2_IMG, W, b, g_a3 + (size_t)n * A3_IMG, cog, task);
}

// Layer 4: A3 -> emb (dense), 12 tasks/img, 10 img/block (120 threads)
__global__ void __launch_bounds__(120, 3)
conv4_k(const float* __restrict__ W, const float* __restrict__ b)
{
    const int il = threadIdx.x / 12;
    const int task = threadIdx.x % 12;
    const int n = blockIdx.y * 10 + il;
    const int cog = blockIdx.x * 16;
    conv_body16<64, A3_RS, A3_PS, 6, 6, 36, 0, 120>(
        g_a3 + (size_t)n * A3_IMG, W, b, g_emb + (size_t)n * DFEAT, cog, task);
}

// Prototypes: proto[b][c][d] = sum_{s: y%5==c} emb / CAP ; plus ||proto||.
__global__ void proto_k(const int* __restrict__ y)
{
    const int b = blockIdx.x / CCLS;
    const int c = blockIdx.x % CCLS;
    const int tid = threadIdx.x;
    __shared__ float sel[SSUP];
    if (tid < SSUP)
        sel[tid] = ((y[b * SSUP + tid] % CCLS) == c) ? 0.2f : 0.f;
    __syncthreads();

    float sq = 0.f;
    for (int d = tid; d < DFEAT; d += 256) {
        float s = 0.f;
#pragma unroll 5
        for (int k = 0; k < SSUP; k++)
            s += sel[k] * g_emb[(size_t)(b * SSUP + k) * DFEAT + d];
        g_protos[(size_t)(b * CCLS + c) * DFEAT + d] = s;
        sq += s * s;
    }
    __shared__ float red[256];
    red[tid] = sq;
    __syncthreads();
    for (int off = 128; off > 0; off >>= 1) {
        if (tid < off) red[tid] += red[tid + off];
        __syncthreads();
    }
    if (tid == 0) g_pnorm[blockIdx.x] = sqrtf(red[0]);
}

// Cosine logits
__global__ void preds_k(float* __restrict__ out)
{
    const int bt = blockIdx.x;
    const int b  = bt / TTGT;
    const int tid = threadIdx.x;
    const float* te = g_emb + (size_t)(NSUP + bt) * DFEAT;
    const float* pr = g_protos + (size_t)b * CCLS * DFEAT;

    float dot[CCLS] = {0.f, 0.f, 0.f, 0.f, 0.f};
    float nn = 0.f;
    for (int d = tid; d < DFEAT; d += 128) {
        const float tv = te[d];
        nn += tv * tv;
#pragma unroll
        for (int c = 0; c < CCLS; c++)
            dot[c] += tv * pr[(size_t)c * DFEAT + d];
    }

    __shared__ float red[6][128];
    red[0][tid] = nn;
#pragma unroll
    for (int c = 0; c < CCLS; c++) red[c + 1][tid] = dot[c];
    __syncthreads();
    for (int off = 64; off > 0; off >>= 1) {
        if (tid < off) {
#pragma unroll
            for (int j = 0; j < 6; j++) red[j][tid] += red[j][tid + off];
        }
        __syncthreads();
    }
    if (tid < CCLS) {
        const float tn = fmaxf(sqrtf(red[0][0]), EPSN);
        const float pn = fmaxf(g_pnorm[b * CCLS + tid], EPSN);
        out[bt * CCLS + tid] = red[1 + tid][0] / (tn * pn);
    }
}

extern "C" void kernel_launch(void* const* d_in, const int* in_sizes, int n_in,
                              void* d_out, int out_size)
{
    (void)in_sizes; (void)n_in; (void)out_size;
    const float* xs = (const float*)d_in[0];
    const float* xt = (const float*)d_in[1];
    const int*   y  = (const int*)d_in[2];
    const float* W1 = (const float*)d_in[3];
    const float* b1 = (const float*)d_in[4];
    const float* W2 = (const float*)d_in[5];
    const float* b2 = (const float*)d_in[6];
    const float* W3 = (const float*)d_in[7];
    const float* b3 = (const float*)d_in[8];
    const float* W4 = (const float*)d_in[9];
    const float* b4 = (const float*)d_in[10];
    float* out = (float*)d_out;

    zero_borders_k<<<dim3(34400, 3), 256>>>();

    // conv1: COG=16 -> 4 cog groups, 4 task chunks of 128 (462 tasks/img)
    conv1_k<<<dim3(4, 4, NIMG), 128>>>(xs, xt, W1, b1);
    conv2_k<<<dim3(4, NIMG), 128>>>(W2, b2);
    conv3_k<<<dim3(4, NIMG / 4), 132>>>(W3, b3);
    conv4_k<<<dim3(4, NIMG / 10), 120>>>(W4, b4);

    proto_k<<<BN * CCLS, 256>>>(y);
    preds_k<<<BN * TTGT, 128>>>(out);
}

// round 15
// speedup vs baseline: 1.1665x; 1.0227x over previous
#include <cuda_runtime.h>
#include <math.h>

#define BN    8
#define SSUP  25
#define TTGT  75
#define CCLS  5
#define NIMG  800     // 200 support + 600 target
#define NSUP  200
#define DFEAT 2304
#define EPSN  1e-8f

typedef unsigned long long u64;

// Padded intermediate layouts (zero borders, vector-load friendly).
// Borders are NEVER written by any kernel and device globals are
// zero-initialized at module load -> they are permanently zero; no
// runtime border-zeroing needed.
// A1: [64][44][44] valid [0..41][0..41]
// A2: [64][24][24] valid at [h+1][w+1], h,w<=20
// A3: [64][14][16] valid at [h+1][w+1], h,w<=10
#define A1_RS 44
#define A1_PS (44*44)
#define A1_IMG (64*A1_PS)
#define A2_RS 24
#define A2_PS (24*24)
#define A2_IMG (64*A2_PS)
#define A3_RS 16
#define A3_PS (14*16)
#define A3_IMG (64*A3_PS)

__device__ __align__(16) float g_a1[NIMG * A1_IMG + 64];
__device__ __align__(16) float g_a2[NIMG * A2_IMG + 64];
__device__ __align__(16) float g_a3[NIMG * A3_IMG + 64];
__device__ __align__(16) float g_emb[NIMG * DFEAT];
__device__ float g_protos[BN * CCLS * DFEAT];
__device__ float g_pnorm[BN * CCLS];

// ---- packed f32x2 helpers (sm_103a FFMA2 path) ----
__device__ __forceinline__ u64 dup2(float v) {
    u64 r; unsigned u = __float_as_uint(v);
    asm("mov.b64 %0, {%1, %2};" : "=l"(r) : "r"(u), "r"(u));
    return r;
}
__device__ __forceinline__ u64 fma2(u64 a, u64 b, u64 c) {
    u64 d;
    asm("fma.rn.f32x2 %0, %1, %2, %3;" : "=l"(d) : "l"(a), "l"(b), "l"(c));
    return d;
}
__device__ __forceinline__ float2 unpack2(u64 v) {
    unsigned lo, hi;
    asm("mov.b64 {%0, %1}, %2;" : "=r"(lo), "=r"(hi) : "l"(v));
    return make_float2(__uint_as_float(lo), __uint_as_float(hi));
}

// Direct conv, padded input, stride 2, 3x3, no bounds checks.
// COG=16: each thread computes 16 output channels (8 FFMA2 oc-pairs) x 4
// pixels. Weights in smem as [cin][k][oc16], read as broadcast LDS.128.
template <int CIN, int RS, int PS, int HOUT, int ORS, int OPS, int OSH, int TPB>
__device__ __forceinline__ void conv_body16(
    const float* __restrict__ base,
    const float* __restrict__ W,
    const float* __restrict__ bias,
    float* __restrict__ outp,
    int cog, int task)
{
    constexpr int WT = (HOUT + 3) / 4;
    const int tid = threadIdx.x;

    __shared__ __align__(16) float sw[16 * CIN * 9];  // [cin][k][oc16]
    for (int i = tid; i < 16 * CIN * 9; i += TPB) {
        const int oc  = i & 15;
        const int k   = (i >> 4) % 9;
        const int cin = i / 144;
        sw[i] = __ldg(W + ((size_t)(cog + oc) * CIN + cin) * 9 + k);
    }
    __syncthreads();

    if (task >= HOUT * WT) return;
    const int h  = task / WT;
    const int w0 = (task % WT) * 4;
    const int r0 = 2 * h;
    const int c0 = 2 * w0;

    u64 acc[8][4];
#pragma unroll
    for (int q = 0; q < 8; q++)
#pragma unroll
        for (int p = 0; p < 4; p++) acc[q][p] = 0ull;

    const float* ip0 = base + (size_t)r0 * RS + c0;

#pragma unroll 2
    for (int cin = 0; cin < CIN; cin++) {
        const float* ip = ip0 + (size_t)cin * PS;
#pragma unroll
        for (int kh = 0; kh < 3; kh++) {
            float fv[12];
#pragma unroll
            for (int v = 0; v < 3; v++)
                *(float4*)&fv[v * 4] = *(const float4*)(ip + kh * RS + v * 4);
            u64 dv[9];
#pragma unroll
            for (int j = 0; j < 9; j++) dv[j] = dup2(fv[j]);
#pragma unroll
            for (int kw = 0; kw < 3; kw++) {
                const ulonglong2* wrow =
                    (const ulonglong2*)&sw[(cin * 9 + kh * 3 + kw) * 16];
                const ulonglong2 wA = wrow[0];
                const ulonglong2 wB = wrow[1];
                const ulonglong2 wC = wrow[2];
                const ulonglong2 wD = wrow[3];
                const u64 wp[8] = {wA.x, wA.y, wB.x, wB.y, wC.x, wC.y, wD.x, wD.y};
#pragma unroll
                for (int q = 0; q < 8; q++)
#pragma unroll
                    for (int p = 0; p < 4; p++)
                        acc[q][p] = fma2(dv[2 * p + kw], wp[q], acc[q][p]);
            }
        }
    }

#pragma unroll
    for (int q = 0; q < 8; q++) {
        const int co0 = cog + 2 * q;
        const float b0 = __ldg(bias + co0);
        const float b1 = __ldg(bias + co0 + 1);
#pragma unroll
        for (int p = 0; p < 4; p++) {
            const int w = w0 + p;
            if (w < HOUT) {
                const float2 v = unpack2(acc[q][p]);
                outp[((size_t)co0       * OPS) + (h + OSH) * ORS + (w + OSH)] = fmaxf(v.x + b0, 0.f);
                outp[((size_t)(co0 + 1) * OPS) + (h + OSH) * ORS + (w + OSH)] = fmaxf(v.y + b1, 0.f);
            }
        }
    }
}

// Layer 1 (harness input, unpadded -> masked scalar loads), COG=16,
// writes padded A1. blockIdx: x = task chunk, y = cog16 group, z = image.
__global__ void __launch_bounds__(128)
conv1_k(const float* __restrict__ xs, const float* __restrict__ xt,
        const float* __restrict__ W, const float* __restrict__ b)
{
    const int n   = blockIdx.z;
    const int cog = blockIdx.y * 16;
    const int tid = threadIdx.x;
    const int task = blockIdx.x * 128 + tid;

    __shared__ __align__(16) float sw[16 * 3 * 9];   // [cin][k][oc16]
    for (int i = tid; i < 16 * 3 * 9; i += 128) {
        const int oc = i & 15, k = (i >> 4) % 9, cin = i / 144;
        sw[i] = __ldg(W + ((size_t)(cog + oc) * 3 + cin) * 9 + k);
    }
    __syncthreads();

    if (task >= 42 * 11) return;
    const int h  = task / 11;
    const int w0 = (task % 11) * 4;
    const int r0 = 2 * h, c0 = 2 * w0;

    const float* base = (n < NSUP) ? xs + (size_t)n * 3 * 84 * 84
                                   : xt + (size_t)(n - NSUP) * 3 * 84 * 84;
    float* outp = g_a1 + (size_t)n * A1_IMG;

    u64 acc[8][4];
#pragma unroll
    for (int q = 0; q < 8; q++)
#pragma unroll
        for (int p = 0; p < 4; p++) acc[q][p] = 0ull;

#pragma unroll
    for (int cin = 0; cin < 3; cin++) {
        const float* ip = base + (size_t)cin * 84 * 84;
#pragma unroll
        for (int kh = 0; kh < 3; kh++) {
            const int r = r0 + kh;
            const bool rok = (r < 84);
            u64 dv[9];
#pragma unroll
            for (int kc = 0; kc < 9; kc++) {
                const int c = c0 + kc;
                const float v = (rok && c < 84) ? __ldg(ip + r * 84 + c) : 0.f;
                dv[kc] = dup2(v);
            }
#pragma unroll
            for (int kw = 0; kw < 3; kw++) {
                const ulonglong2* wrow =
                    (const ulonglong2*)&sw[(cin * 9 + kh * 3 + kw) * 16];
                const ulonglong2 wA = wrow[0];
                const ulonglong2 wB = wrow[1];
                const ulonglong2 wC = wrow[2];
                const ulonglong2 wD = wrow[3];
                const u64 wp[8] = {wA.x, wA.y, wB.x, wB.y, wC.x, wC.y, wD.x, wD.y};
#pragma unroll
                for (int q = 0; q < 8; q++)
#pragma unroll
                    for (int p = 0; p < 4; p++)
                        acc[q][p] = fma2(dv[2 * p + kw], wp[q], acc[q][p]);
            }
        }
    }

#pragma unroll
    for (int q = 0; q < 8; q++) {
        const int co0 = cog + 2 * q;
        const float b0 = __ldg(b + co0);
        const float b1 = __ldg(b + co0 + 1);
#pragma unroll
        for (int p = 0; p < 4; p++) {
            const int w = w0 + p;
            if (w < 42) {
                const float2 v = unpack2(acc[q][p]);
                outp[(size_t)co0       * A1_PS + h * A1_RS + w] = fmaxf(v.x + b0, 0.f);
                outp[(size_t)(co0 + 1) * A1_PS + h * A1_RS + w] = fmaxf(v.y + b1, 0.f);
            }
        }
    }
}

// Layer 2 (smem-staged, double-buffered): block = (cog16 group, image),
// 126 threads = tasks. Chunks of 2 cin planes staged in smem via
// coalesced LDG->reg prefetch + STS; compute reads LDS. Weights staged
// per-chunk [cl][k][oc16], double-buffered.
#define C2_CHF (2 * A1_PS)        // floats per input chunk (3872)
#define C2_CV4 (C2_CHF / 4)       // float4 per input chunk (968)
#define C2_WF  (2 * 9 * 16)       // weight floats per chunk (288)
__global__ void __launch_bounds__(126)
conv2s_k(const float* __restrict__ W, const float* __restrict__ bias)
{
    const int n   = blockIdx.y;
    const int cog = blockIdx.x * 16;
    const int tid = threadIdx.x;

    __shared__ __align__(16) float si[2][C2_CHF];
    __shared__ __align__(16) float sww[2][C2_WF];

    const float* base = g_a1 + (size_t)n * A1_IMG;

    const int h  = tid / 6;           // 0..20
    const int w0 = (tid % 6) * 4;     // 0..20
    const int r0 = 2 * h, c0 = 2 * w0;

    // chunk 0 staged directly
    {
        const float4* gs = (const float4*)base;
        for (int i = tid; i < C2_CV4; i += 126)
            ((float4*)si[0])[i] = gs[i];
        for (int i = tid; i < C2_WF; i += 126) {
            const int oc = i & 15, k = (i >> 4) % 9, cl = i / 144;
            sww[0][i] = __ldg(W + ((size_t)(cog + oc) * 64 + cl) * 9 + k);
        }
    }
    __syncthreads();

    u64 acc[8][4];
#pragma unroll
    for (int q = 0; q < 8; q++)
#pragma unroll
        for (int p = 0; p < 4; p++) acc[q][p] = 0ull;

    float4 pin[8];
    float  pwf[3];

#pragma unroll 1
    for (int cc = 0; cc < 32; cc++) {
        const int cb = cc & 1, nb = (cc + 1) & 1;
        // prefetch next chunk into registers (LDG in flight during compute)
        if (cc < 31) {
            const float4* gs = (const float4*)(base + (size_t)(2 * (cc + 1)) * A1_PS);
#pragma unroll
            for (int j = 0; j < 8; j++) {
                const int i = tid + j * 126;
                if (i < C2_CV4) pin[j] = gs[i];
            }
#pragma unroll
            for (int j = 0; j < 3; j++) {
                const int i = tid + j * 126;
                if (i < C2_WF) {
                    const int oc = i & 15, k = (i >> 4) % 9, cl = i / 144;
                    pwf[j] = __ldg(W + ((size_t)(cog + oc) * 64 + (2 * (cc + 1) + cl)) * 9 + k);
                }
            }
        }
        // compute current chunk (2 cin planes from smem)
#pragma unroll
        for (int cl = 0; cl < 2; cl++) {
            const float* ip = &si[cb][cl * A1_PS] + r0 * A1_RS + c0;
#pragma unroll
            for (int kh = 0; kh < 3; kh++) {
                float fv[12];
#pragma unroll
                for (int v = 0; v < 3; v++)
                    *(float4*)&fv[v * 4] = *(const float4*)(ip + kh * A1_RS + v * 4);
                u64 dv[9];
#pragma unroll
                for (int j = 0; j < 9; j++) dv[j] = dup2(fv[j]);
#pragma unroll
                for (int kw = 0; kw < 3; kw++) {
                    const ulonglong2* wrow =
                        (const ulonglong2*)&sww[cb][cl * 144 + (kh * 3 + kw) * 16];
                    const ulonglong2 wA = wrow[0];
                    const ulonglong2 wB = wrow[1];
                    const ulonglong2 wC = wrow[2];
                    const ulonglong2 wD = wrow[3];
                    const u64 wp[8] = {wA.x, wA.y, wB.x, wB.y, wC.x, wC.y, wD.x, wD.y};
#pragma unroll
                    for (int q = 0; q < 8; q++)
#pragma unroll
                        for (int p = 0; p < 4; p++)
                            acc[q][p] = fma2(dv[2 * p + kw], wp[q], acc[q][p]);
                }
            }
        }
        __syncthreads();   // everyone done reading buf nb (last used chunk cc-1)
        if (cc < 31) {
#pragma unroll
            for (int j = 0; j < 8; j++) {
                const int i = tid + j * 126;
                if (i < C2_CV4) ((float4*)si[nb])[i] = pin[j];
            }
#pragma unroll
            for (int j = 0; j < 3; j++) {
                const int i = tid + j * 126;
                if (i < C2_WF) sww[nb][i] = pwf[j];
            }
            __syncthreads();
        }
    }

    float* outp = g_a2 + (size_t)n * A2_IMG;
#pragma unroll
    for (int q = 0; q < 8; q++) {
        const int co0 = cog + 2 * q;
        const float b0 = __ldg(bias + co0);
        const float b1 = __ldg(bias + co0 + 1);
#pragma unroll
        for (int p = 0; p < 4; p++) {
            const int w = w0 + p;
            if (w < 21) {
                const float2 v = unpack2(acc[q][p]);
                outp[(size_t)co0       * A2_PS + (h + 1) * A2_RS + (w + 1)] = fmaxf(v.x + b0, 0.f);
                outp[(size_t)(co0 + 1) * A2_PS + (h + 1) * A2_RS + (w + 1)] = fmaxf(v.y + b1, 0.f);
            }
        }
    }
}

// Layer 3: A2 -> A3, 33 tasks/img, 4 img/block (132 threads)
__global__ void __launch_bounds__(132, 3)
conv3_k(const float* __restrict__ W, const float* __restrict__ b)
{
    const int il = threadIdx.x / 33;
    const int task = threadIdx.x % 33;
    const int n = blockIdx.y * 4 + il;
    const int cog = blockIdx.x * 16;
    conv_body16<64, A2_RS, A2_PS, 11, A3_RS, A3_PS, 1, 132>(
        g_a2 + (size_t)n * A2_IMG, W, b, g_a3 + (size_t)n * A3_IMG, cog, task);
}

// Layer 4: A3 -> emb (dense), 12 tasks/img, 10 img/block (120 threads)
__global__ void __launch_bounds__(120, 3)
conv4_k(const float* __restrict__ W, const float* __restrict__ b)
{
    const int il = threadIdx.x / 12;
    const int task = threadIdx.x % 12;
    const int n = blockIdx.y * 10 + il;
    const int cog = blockIdx.x * 16;
    conv_body16<64, A3_RS, A3_PS, 6, 6, 36, 0, 120>(
        g_a3 + (size_t)n * A3_IMG, W, b, g_emb + (size_t)n * DFEAT, cog, task);
}

// Prototypes: proto[b][c][d] = sum_{s: y%5==c} emb / CAP ; plus ||proto||.
__global__ void proto_k(const int* __restrict__ y)
{
    const int b = blockIdx.x / CCLS;
    const int c = blockIdx.x % CCLS;
    const int tid = threadIdx.x;
    __shared__ float sel[SSUP];
    if (tid < SSUP)
        sel[tid] = ((y[b * SSUP + tid] % CCLS) == c) ? 0.2f : 0.f;
    __syncthreads();

    float sq = 0.f;
    for (int d = tid; d < DFEAT; d += 256) {
        float s = 0.f;
#pragma unroll 5
        for (int k = 0; k < SSUP; k++)
            s += sel[k] * g_emb[(size_t)(b * SSUP + k) * DFEAT + d];
        g_protos[(size_t)(b * CCLS + c) * DFEAT + d] = s;
        sq += s * s;
    }
    __shared__ float red[256];
    red[tid] = sq;
    __syncthreads();
    for (int off = 128; off > 0; off >>= 1) {
        if (tid < off) red[tid] += red[tid + off];
        __syncthreads();
    }
    if (tid == 0) g_pnorm[blockIdx.x] = sqrtf(red[0]);
}

// Cosine logits
__global__ void preds_k(float* __restrict__ out)
{
    const int bt = blockIdx.x;
    const int b  = bt / TTGT;
    const int tid = threadIdx.x;
    const float* te = g_emb + (size_t)(NSUP + bt) * DFEAT;
    const float* pr = g_protos + (size_t)b * CCLS * DFEAT;

    float dot[CCLS] = {0.f, 0.f, 0.f, 0.f, 0.f};
    float nn = 0.f;
    for (int d = tid; d < DFEAT; d += 128) {
        const float tv = te[d];
        nn += tv * tv;
#pragma unroll
        for (int c = 0; c < CCLS; c++)
            dot[c] += tv * pr[(size_t)c * DFEAT + d];
    }

    __shared__ float red[6][128];
    red[0][tid] = nn;
#pragma unroll
    for (int c = 0; c < CCLS; c++) red[c + 1][tid] = dot[c];
    __syncthreads();
    for (int off = 64; off > 0; off >>= 1) {
        if (tid < off) {
#pragma unroll
            for (int j = 0; j < 6; j++) red[j][tid] += red[j][tid + off];
        }
        __syncthreads();
    }
    if (tid < CCLS) {
        const float tn = fmaxf(sqrtf(red[0][0]), EPSN);
        const float pn = fmaxf(g_pnorm[b * CCLS + tid], EPSN);
        out[bt * CCLS + tid] = red[1 + tid][0] / (tn * pn);
    }
}

extern "C" void kernel_launch(void* const* d_in, const int* in_sizes, int n_in,
                              void* d_out, int out_size)
{
    (void)in_sizes; (void)n_in; (void)out_size;
    const float* xs = (const float*)d_in[0];
    const float* xt = (const float*)d_in[1];
    const int*   y  = (const int*)d_in[2];
    const float* W1 = (const float*)d_in[3];
    const float* b1 = (const float*)d_in[4];
    const float* W2 = (const float*)d_in[5];
    const float* b2 = (const float*)d_in[6];
    const float* W3 = (const float*)d_in[7];
    const float* b3 = (const float*)d_in[8];
    const float* W4 = (const float*)d_in[9];
    const float* b4 = (const float*)d_in[10];
    float* out = (float*)d_out;

    // conv1: COG=16 -> 4 cog groups, 4 task chunks of 128 (462 tasks/img)
    conv1_k<<<dim3(4, 4, NIMG), 128>>>(xs, xt, W1, b1);
    conv2s_k<<<dim3(4, NIMG), 126>>>(W2, b2);
    conv3_k<<<dim3(4, NIMG / 4), 132>>>(W3, b3);
    conv4_k<<<dim3(4, NIMG / 10), 120>>>(W4, b4);

    proto_k<<<BN * CCLS, 256>>>(y);
    preds_k<<<BN * TTGT, 128>>>(out);
}